// round 1
// baseline (speedup 1.0000x reference)
#include <cuda_runtime.h>

#define N_NODES 100000
#define N_EDGES 1600000
#define NODE_DIM 64
#define HIDDEN 256
#define OUT_DIM 64
#define BN_EPS 1e-5f

// Scratch (device globals — no allocation allowed)
__device__ float g_agg[N_NODES * NODE_DIM];   // 25.6 MB segment-sum accumulator
__device__ float g_deg[N_NODES];
__device__ float g_colsum[OUT_DIM];
__device__ float g_colsq[OUT_DIM];

typedef unsigned long long u64;

__device__ __forceinline__ u64 pack2(float lo, float hi) {
    u64 r; asm("mov.b64 %0, {%1, %2};" : "=l"(r) : "f"(lo), "f"(hi)); return r;
}
__device__ __forceinline__ void unpack2(u64 v, float& lo, float& hi) {
    asm("mov.b64 {%0, %1}, %2;" : "=f"(lo), "=f"(hi) : "l"(v));
}
// Packed f32x2 FMA (FFMA2) — 2 MACs per lane per instruction; only reachable via PTX.
#define FMA2(d, a, b) asm("fma.rn.f32x2 %0, %1, %2, %0;" : "+l"(d) : "l"(a), "l"(b))

// ---------------------------------------------------------------------------
// Kernel 0: zero the scratch accumulators
// ---------------------------------------------------------------------------
__global__ void zero_kernel() {
    int i = blockIdx.x * blockDim.x + threadIdx.x;
    int stride = gridDim.x * blockDim.x;
    const int AGG = N_NODES * NODE_DIM;
    const int total = AGG + N_NODES + 2 * OUT_DIM;
    for (; i < total; i += stride) {
        if (i < AGG) g_agg[i] = 0.0f;
        else if (i < AGG + N_NODES) g_deg[i - AGG] = 0.0f;
        else {
            int j = i - AGG - N_NODES;
            if (j < OUT_DIM) g_colsum[j] = 0.0f;
            else g_colsq[j - OUT_DIM] = 0.0f;
        }
    }
}

// ---------------------------------------------------------------------------
// Kernel 1: edge scatter — 16 threads per edge, each owns one float4 chunk.
// Vector RED (red.global.add.v4.f32) quarters the atomic-op count.
// ---------------------------------------------------------------------------
__global__ void edge_kernel(const float4* __restrict__ h4,
                            const int* __restrict__ src,
                            const int* __restrict__ dst) {
    int t = blockIdx.x * 256 + threadIdx.x;
    int e = t >> 4;
    if (e >= N_EDGES) return;
    int c = t & 15;
    int s = __ldg(src + e);
    int d = __ldg(dst + e);
    float4 v = __ldg(h4 + s * 16 + c);
    float* p = g_agg + (d << 6) + (c << 2);
    asm volatile("red.global.add.v4.f32 [%0], {%1, %2, %3, %4};"
                 :: "l"(p), "f"(v.x), "f"(v.y), "f"(v.z), "f"(v.w) : "memory");
    if (c == 0) atomicAdd(g_deg + d, 1.0f);
}

// ---------------------------------------------------------------------------
// Kernel 2: fused combine + 2-layer MLP. One node per thread; W1/W2 broadcast
// from smem; all FMAs are packed f32x2 (FFMA2). Hidden activations are
// streamed in tiles of 8 — never materialized.
// ---------------------------------------------------------------------------
__global__ void __launch_bounds__(256, 1)
mlp_kernel(const float* __restrict__ h,
           const float* __restrict__ W1, const float* __restrict__ b1,
           const float* __restrict__ W2, const float* __restrict__ b2,
           float* __restrict__ out) {
    extern __shared__ float smem[];
    float* W1s = smem;                     // 64*256
    float* W2s = smem + 64 * 256;          // 256*64
    float* b1s = W2s + 256 * 64;           // 256
    float* b2s = b1s + 256;                // 64

    for (int i = threadIdx.x; i < 64 * 256 / 4; i += 256) {
        ((float4*)W1s)[i] = ((const float4*)W1)[i];
        ((float4*)W2s)[i] = ((const float4*)W2)[i];
    }
    if (threadIdx.x < 64) b2s[threadIdx.x] = b2[threadIdx.x];
    for (int i = threadIdx.x; i < 256; i += 256) b1s[i] = b1[i];
    __syncthreads();

    int n = blockIdx.x * 256 + threadIdx.x;
    if (n >= N_NODES) return;

    // x = agg / max(deg,1) + h
    float inv = 1.0f / fmaxf(g_deg[n], 1.0f);
    float x[64];
    const float4* a4 = (const float4*)(g_agg + (size_t)n * 64);
    const float4* hv4 = (const float4*)(h + (size_t)n * 64);
#pragma unroll
    for (int q = 0; q < 16; q++) {
        float4 a = a4[q];
        float4 hv = __ldg(hv4 + q);
        x[4 * q + 0] = fmaf(a.x, inv, hv.x);
        x[4 * q + 1] = fmaf(a.y, inv, hv.y);
        x[4 * q + 2] = fmaf(a.z, inv, hv.z);
        x[4 * q + 3] = fmaf(a.w, inv, hv.w);
    }

    u64 acc[32];  // 64 output accumulators, packed in pairs
#pragma unroll
    for (int q = 0; q < 32; q++) acc[q] = pack2(b2s[2 * q], b2s[2 * q + 1]);

#pragma unroll 1
    for (int j0 = 0; j0 < 256; j0 += 8) {
        u64 hacc[4];  // 8 hidden units, packed
#pragma unroll
        for (int p = 0; p < 4; p++) hacc[p] = pack2(b1s[j0 + 2 * p], b1s[j0 + 2 * p + 1]);
#pragma unroll
        for (int k = 0; k < 64; k++) {
            u64 xk = pack2(x[k], x[k]);
            const ulonglong2* w = (const ulonglong2*)&W1s[k * 256 + j0];
            ulonglong2 w01 = w[0], w23 = w[1];
            FMA2(hacc[0], xk, w01.x);
            FMA2(hacc[1], xk, w01.y);
            FMA2(hacc[2], xk, w23.x);
            FMA2(hacc[3], xk, w23.y);
        }
        // relu + consume into GEMM2
#pragma unroll
        for (int p = 0; p < 4; p++) {
            float h0, h1;
            unpack2(hacc[p], h0, h1);
            h0 = fmaxf(h0, 0.0f);
            h1 = fmaxf(h1, 0.0f);
            u64 h0p = pack2(h0, h0), h1p = pack2(h1, h1);
            const ulonglong2* w0 = (const ulonglong2*)&W2s[(j0 + 2 * p) * 64];
            const ulonglong2* w1 = (const ulonglong2*)&W2s[(j0 + 2 * p + 1) * 64];
#pragma unroll
            for (int q = 0; q < 16; q++) {
                ulonglong2 wa = w0[q], wb = w1[q];
                FMA2(acc[2 * q],     h0p, wa.x);
                FMA2(acc[2 * q + 1], h0p, wa.y);
                FMA2(acc[2 * q],     h1p, wb.x);
                FMA2(acc[2 * q + 1], h1p, wb.y);
            }
        }
    }

    // final relu, store pre-BN result to out
    float4* o4 = (float4*)(out + (size_t)n * 64);
#pragma unroll
    for (int q = 0; q < 16; q++) {
        float a0, a1, a2, a3;
        unpack2(acc[2 * q], a0, a1);
        unpack2(acc[2 * q + 1], a2, a3);
        float4 o;
        o.x = fmaxf(a0, 0.0f);
        o.y = fmaxf(a1, 0.0f);
        o.z = fmaxf(a2, 0.0f);
        o.w = fmaxf(a3, 0.0f);
        o4[q] = o;
    }
}

// ---------------------------------------------------------------------------
// Kernel 3: BN column stats (sum, sumsq). 64 threads/block, one column each,
// coalesced 256B row reads (data is L2-resident from kernel 2).
// ---------------------------------------------------------------------------
__global__ void stats_kernel(const float* __restrict__ y) {
    int c = threadIdx.x;  // 0..63
    float s = 0.0f, sq = 0.0f;
    for (int r = blockIdx.x; r < N_NODES; r += gridDim.x) {
        float v = __ldg(y + (size_t)r * 64 + c);
        s += v;
        sq = fmaf(v, v, sq);
    }
    atomicAdd(g_colsum + c, s);
    atomicAdd(g_colsq + c, sq);
}

// ---------------------------------------------------------------------------
// Kernel 4: normalize in place: (y - mean) * rsqrt(var+eps) * gamma + beta
// ---------------------------------------------------------------------------
__global__ void bn_kernel(float* __restrict__ y,
                          const float* __restrict__ gamma,
                          const float* __restrict__ beta) {
    __shared__ float scale[64], shift[64];
    if (threadIdx.x < 64) {
        int c = threadIdx.x;
        const float invN = 1.0f / (float)N_NODES;
        float mean = g_colsum[c] * invN;
        float var = fmaxf(g_colsq[c] * invN - mean * mean, 0.0f);
        float sc = gamma[c] * rsqrtf(var + BN_EPS);
        scale[c] = sc;
        shift[c] = beta[c] - mean * sc;
    }
    __syncthreads();
    int i = blockIdx.x * blockDim.x + threadIdx.x;
    int stride = gridDim.x * blockDim.x;
    const int total4 = N_NODES * OUT_DIM / 4;
    float4* y4 = (float4*)y;
    for (; i < total4; i += stride) {
        int c4 = (i & 15) * 4;
        float4 v = y4[i];
        v.x = fmaf(v.x, scale[c4 + 0], shift[c4 + 0]);
        v.y = fmaf(v.y, scale[c4 + 1], shift[c4 + 1]);
        v.z = fmaf(v.z, scale[c4 + 2], shift[c4 + 2]);
        v.w = fmaf(v.w, scale[c4 + 3], shift[c4 + 3]);
        y4[i] = v;
    }
}

// ---------------------------------------------------------------------------
extern "C" void kernel_launch(void* const* d_in, const int* in_sizes, int n_in,
                              void* d_out, int out_size) {
    const float* h     = (const float*)d_in[0];
    const float* W1    = (const float*)d_in[1];
    const float* b1    = (const float*)d_in[2];
    const float* W2    = (const float*)d_in[3];
    const float* b2    = (const float*)d_in[4];
    const float* gamma = (const float*)d_in[5];
    const float* beta  = (const float*)d_in[6];
    const int*   src   = (const int*)d_in[7];
    const int*   dst   = (const int*)d_in[8];
    float* out = (float*)d_out;

    const size_t SMEM = (size_t)(64 * 256 + 256 * 64 + 256 + 64) * sizeof(float);
    // Idempotent, deterministic; needed because 132 KB > default 48 KB.
    cudaFuncSetAttribute(mlp_kernel, cudaFuncAttributeMaxDynamicSharedMemorySize, (int)SMEM);

    zero_kernel<<<2048, 256>>>();
    edge_kernel<<<(N_EDGES * 16) / 256, 256>>>((const float4*)h, src, dst);
    mlp_kernel<<<(N_NODES + 255) / 256, 256, SMEM>>>(h, W1, b1, W2, b2, out);
    stats_kernel<<<1024, 64>>>(out);
    bn_kernel<<<4096, 256>>>(out, gamma, beta);
}

// round 2
// speedup vs baseline: 1.1660x; 1.1660x over previous
#include <cuda_runtime.h>

#define N_NODES 100000
#define N_EDGES 1600000
#define NODE_DIM 64
#define HIDDEN 256
#define OUT_DIM 64
#define BN_EPS 1e-5f

// ---- device scratch (no allocation allowed) ----
__device__ float g_x[N_NODES * NODE_DIM];     // combined input x = agg/deg + h (25.6 MB)
__device__ int   g_cnt[N_NODES];              // in-degree counts
__device__ int   g_off[N_NODES + 1];          // CSR offsets
__device__ int   g_woff[N_NODES];             // working offsets for scatter
__device__ int   g_esrc[N_EDGES];             // CSR edge sources
__device__ int   g_bsum[256];                 // scan block sums
__device__ int   g_boff[256];                 // scan block offsets
__device__ float g_colsum[OUT_DIM];
__device__ float g_colsq[OUT_DIM];

typedef unsigned long long u64;

__device__ __forceinline__ u64 pack2(float lo, float hi) {
    u64 r; asm("mov.b64 %0, {%1, %2};" : "=l"(r) : "f"(lo), "f"(hi)); return r;
}
__device__ __forceinline__ void unpack2(u64 v, float& lo, float& hi) {
    asm("mov.b64 {%0, %1}, %2;" : "=f"(lo), "=f"(hi) : "l"(v));
}
// Packed f32x2 FMA — 2 MACs/lane/inst; only reachable via PTX.
#define FMA2(d, a, b) asm("fma.rn.f32x2 %0, %1, %2, %0;" : "+l"(d) : "l"(a), "l"(b))

// ---------------------------------------------------------------------------
// 0: zero counters
// ---------------------------------------------------------------------------
__global__ void zero_kernel() {
    int i = blockIdx.x * 256 + threadIdx.x;
    if (i < N_NODES) g_cnt[i] = 0;
    if (i < OUT_DIM) { g_colsum[i] = 0.0f; g_colsq[i] = 0.0f; }
    if (i == 0) g_off[N_NODES] = N_EDGES;
}

// ---------------------------------------------------------------------------
// 1: in-degree histogram
// ---------------------------------------------------------------------------
__global__ void count_kernel(const int* __restrict__ dst) {
    int i = blockIdx.x * 256 + threadIdx.x;
    if (i < N_EDGES) atomicAdd(&g_cnt[dst[i]], 1);
}

// ---------------------------------------------------------------------------
// 2a: per-block sums of counts (512 elems/block)
// ---------------------------------------------------------------------------
__global__ void scan1_kernel() {
    __shared__ int ws[16];
    int i = blockIdx.x * 512 + threadIdx.x;
    int v = (i < N_NODES) ? g_cnt[i] : 0;
#pragma unroll
    for (int d = 16; d; d >>= 1) v += __shfl_down_sync(0xffffffffu, v, d);
    if ((threadIdx.x & 31) == 0) ws[threadIdx.x >> 5] = v;
    __syncthreads();
    if (threadIdx.x == 0) {
        int s = 0;
#pragma unroll
        for (int k = 0; k < 16; k++) s += ws[k];
        g_bsum[blockIdx.x] = s;
    }
}

// ---------------------------------------------------------------------------
// 2b: single-block scan of block sums (nb <= 256)
// ---------------------------------------------------------------------------
__global__ void scan2_kernel(int nb) {
    __shared__ int sm[256];
    int t = threadIdx.x;
    int v = (t < nb) ? g_bsum[t] : 0;
    sm[t] = v;
    __syncthreads();
    for (int d = 1; d < 256; d <<= 1) {
        int y = (t >= d) ? sm[t - d] : 0;
        __syncthreads();
        sm[t] += y;
        __syncthreads();
    }
    if (t < nb) g_boff[t] = sm[t] - v;  // exclusive
}

// ---------------------------------------------------------------------------
// 2c: block-level exclusive scan + global offset -> CSR offsets
// ---------------------------------------------------------------------------
__global__ void scan3_kernel() {
    __shared__ int ws[16];
    int t = threadIdx.x, lane = t & 31, wid = t >> 5;
    int i = blockIdx.x * 512 + t;
    int c = (i < N_NODES) ? g_cnt[i] : 0;
    int x = c;
#pragma unroll
    for (int d = 1; d < 32; d <<= 1) {
        int y = __shfl_up_sync(0xffffffffu, x, d);
        if (lane >= d) x += y;
    }
    if (lane == 31) ws[wid] = x;
    __syncthreads();
    if (wid == 0) {
        int w = (lane < 16) ? ws[lane] : 0;
        int xs = w;
#pragma unroll
        for (int d = 1; d < 16; d <<= 1) {
            int y = __shfl_up_sync(0xffffffffu, xs, d);
            if (lane >= d) xs += y;
        }
        if (lane < 16) ws[lane] = xs - w;  // exclusive warp offsets
    }
    __syncthreads();
    int excl = x - c + ws[wid] + g_boff[blockIdx.x];
    if (i < N_NODES) { g_off[i] = excl; g_woff[i] = excl; }
}

// ---------------------------------------------------------------------------
// 3: scatter edges into CSR bins
// ---------------------------------------------------------------------------
__global__ void scatter_kernel(const int* __restrict__ src,
                               const int* __restrict__ dst) {
    int i = blockIdx.x * 256 + threadIdx.x;
    if (i >= N_EDGES) return;
    int d = dst[i];
    int pos = atomicAdd(&g_woff[d], 1);
    g_esrc[pos] = src[i];
}

// ---------------------------------------------------------------------------
// 4: warp-per-node gather + mean + combine:  g_x = agg/max(deg,1) + h
//    No atomics; each lane owns 2 feature columns (float2 = 256B/warp/edge).
// ---------------------------------------------------------------------------
__global__ void agg_kernel(const float* __restrict__ h) {
    int n = (blockIdx.x * 256 + threadIdx.x) >> 5;
    if (n >= N_NODES) return;
    int lane = threadIdx.x & 31;
    int beg = __ldg(&g_off[n]);
    int end = __ldg(&g_off[n + 1]);
    float ax = 0.0f, ay = 0.0f;
    for (int j = beg; j < end; j += 32) {
        int r = end - j;
        int s_l = 0;
        if (lane < r) s_l = __ldg(&g_esrc[j + lane]);
        int cnt = r < 32 ? r : 32;
        for (int jj = 0; jj < cnt; jj++) {
            int s = __shfl_sync(0xffffffffu, s_l, jj);
            float2 v = *(const float2*)(h + ((size_t)s << 6) + (lane << 1));
            ax += v.x;
            ay += v.y;
        }
    }
    float inv = 1.0f / fmaxf((float)(end - beg), 1.0f);
    float2 hv = *(const float2*)(h + ((size_t)n << 6) + (lane << 1));
    float2 xv = make_float2(fmaf(ax, inv, hv.x), fmaf(ay, inv, hv.y));
    *(float2*)(g_x + ((size_t)n << 6) + (lane << 1)) = xv;
}

// ---------------------------------------------------------------------------
// 5: fused 2-layer MLP (FFMA2), persistent grid-stride, weights in smem.
// ---------------------------------------------------------------------------
__global__ void __launch_bounds__(256, 1)
mlp_kernel(const float* __restrict__ W1, const float* __restrict__ b1,
           const float* __restrict__ W2, const float* __restrict__ b2,
           float* __restrict__ out) {
    extern __shared__ float smem[];
    float* W1s = smem;                     // 64*256
    float* W2s = smem + 64 * 256;          // 256*64
    float* b1s = W2s + 256 * 64;           // 256
    float* b2s = b1s + 256;                // 64

    for (int i = threadIdx.x; i < 64 * 256 / 4; i += 256) {
        ((float4*)W1s)[i] = ((const float4*)W1)[i];
        ((float4*)W2s)[i] = ((const float4*)W2)[i];
    }
    if (threadIdx.x < 64) b2s[threadIdx.x] = b2[threadIdx.x];
    if (threadIdx.x < 256) b1s[threadIdx.x] = b1[threadIdx.x];
    __syncthreads();

    const int stride = gridDim.x * 256;
    for (int n = blockIdx.x * 256 + threadIdx.x; n < N_NODES; n += stride) {
        float x[64];
        const float4* xv4 = (const float4*)(g_x + (size_t)n * 64);
#pragma unroll
        for (int q = 0; q < 16; q++) {
            float4 v = xv4[q];
            x[4 * q + 0] = v.x; x[4 * q + 1] = v.y;
            x[4 * q + 2] = v.z; x[4 * q + 3] = v.w;
        }

        u64 acc[32];
#pragma unroll
        for (int q = 0; q < 32; q++) acc[q] = pack2(b2s[2 * q], b2s[2 * q + 1]);

#pragma unroll 1
        for (int j0 = 0; j0 < 256; j0 += 8) {
            u64 hacc[4];
#pragma unroll
            for (int p = 0; p < 4; p++) hacc[p] = pack2(b1s[j0 + 2 * p], b1s[j0 + 2 * p + 1]);
#pragma unroll
            for (int k = 0; k < 64; k++) {
                u64 xk = pack2(x[k], x[k]);
                const ulonglong2* w = (const ulonglong2*)&W1s[k * 256 + j0];
                ulonglong2 w01 = w[0], w23 = w[1];
                FMA2(hacc[0], xk, w01.x);
                FMA2(hacc[1], xk, w01.y);
                FMA2(hacc[2], xk, w23.x);
                FMA2(hacc[3], xk, w23.y);
            }
#pragma unroll
            for (int p = 0; p < 4; p++) {
                float h0, h1;
                unpack2(hacc[p], h0, h1);
                h0 = fmaxf(h0, 0.0f);
                h1 = fmaxf(h1, 0.0f);
                u64 h0p = pack2(h0, h0), h1p = pack2(h1, h1);
                const ulonglong2* w0 = (const ulonglong2*)&W2s[(j0 + 2 * p) * 64];
                const ulonglong2* w1 = (const ulonglong2*)&W2s[(j0 + 2 * p + 1) * 64];
#pragma unroll
                for (int q = 0; q < 16; q++) {
                    ulonglong2 wa = w0[q], wb = w1[q];
                    FMA2(acc[2 * q],     h0p, wa.x);
                    FMA2(acc[2 * q + 1], h0p, wa.y);
                    FMA2(acc[2 * q],     h1p, wb.x);
                    FMA2(acc[2 * q + 1], h1p, wb.y);
                }
            }
        }

        float4* o4 = (float4*)(out + (size_t)n * 64);
#pragma unroll
        for (int q = 0; q < 16; q++) {
            float a0, a1, a2, a3;
            unpack2(acc[2 * q], a0, a1);
            unpack2(acc[2 * q + 1], a2, a3);
            float4 o;
            o.x = fmaxf(a0, 0.0f);
            o.y = fmaxf(a1, 0.0f);
            o.z = fmaxf(a2, 0.0f);
            o.w = fmaxf(a3, 0.0f);
            o4[q] = o;
        }
    }
}

// ---------------------------------------------------------------------------
// 6: BN column stats — float4 grid-stride + smem reduction
// ---------------------------------------------------------------------------
__global__ void stats_kernel(const float* __restrict__ y) {
    __shared__ float ss[64], sq[64];
    if (threadIdx.x < 64) { ss[threadIdx.x] = 0.0f; sq[threadIdx.x] = 0.0f; }
    __syncthreads();
    const float4* y4 = (const float4*)y;
    const int total = N_NODES * 16;
    int i0 = blockIdx.x * 256 + threadIdx.x;
    int c4 = (i0 & 15) << 2;  // stride is a multiple of 16 -> column group fixed
    float4 s = make_float4(0.f, 0.f, 0.f, 0.f);
    float4 q = make_float4(0.f, 0.f, 0.f, 0.f);
    for (int i = i0; i < total; i += gridDim.x * 256) {
        float4 v = y4[i];
        s.x += v.x; s.y += v.y; s.z += v.z; s.w += v.w;
        q.x = fmaf(v.x, v.x, q.x);
        q.y = fmaf(v.y, v.y, q.y);
        q.z = fmaf(v.z, v.z, q.z);
        q.w = fmaf(v.w, v.w, q.w);
    }
    atomicAdd(&ss[c4 + 0], s.x); atomicAdd(&ss[c4 + 1], s.y);
    atomicAdd(&ss[c4 + 2], s.z); atomicAdd(&ss[c4 + 3], s.w);
    atomicAdd(&sq[c4 + 0], q.x); atomicAdd(&sq[c4 + 1], q.y);
    atomicAdd(&sq[c4 + 2], q.z); atomicAdd(&sq[c4 + 3], q.w);
    __syncthreads();
    if (threadIdx.x < 64) {
        atomicAdd(&g_colsum[threadIdx.x], ss[threadIdx.x]);
        atomicAdd(&g_colsq[threadIdx.x], sq[threadIdx.x]);
    }
}

// ---------------------------------------------------------------------------
// 7: BN apply in place
// ---------------------------------------------------------------------------
__global__ void bn_kernel(float* __restrict__ y,
                          const float* __restrict__ gamma,
                          const float* __restrict__ beta) {
    __shared__ float scale[64], shift[64];
    if (threadIdx.x < 64) {
        int c = threadIdx.x;
        const float invN = 1.0f / (float)N_NODES;
        float mean = g_colsum[c] * invN;
        float var = fmaxf(g_colsq[c] * invN - mean * mean, 0.0f);
        float sc = gamma[c] * rsqrtf(var + BN_EPS);
        scale[c] = sc;
        shift[c] = beta[c] - mean * sc;
    }
    __syncthreads();
    int i = blockIdx.x * blockDim.x + threadIdx.x;
    int stride = gridDim.x * blockDim.x;
    const int total4 = N_NODES * OUT_DIM / 4;
    float4* y4 = (float4*)y;
    for (; i < total4; i += stride) {
        int c4 = (i & 15) * 4;
        float4 v = y4[i];
        v.x = fmaf(v.x, scale[c4 + 0], shift[c4 + 0]);
        v.y = fmaf(v.y, scale[c4 + 1], shift[c4 + 1]);
        v.z = fmaf(v.z, scale[c4 + 2], shift[c4 + 2]);
        v.w = fmaf(v.w, scale[c4 + 3], shift[c4 + 3]);
        y4[i] = v;
    }
}

// ---------------------------------------------------------------------------
extern "C" void kernel_launch(void* const* d_in, const int* in_sizes, int n_in,
                              void* d_out, int out_size) {
    const float* h     = (const float*)d_in[0];
    const float* W1    = (const float*)d_in[1];
    const float* b1    = (const float*)d_in[2];
    const float* W2    = (const float*)d_in[3];
    const float* b2    = (const float*)d_in[4];
    const float* gamma = (const float*)d_in[5];
    const float* beta  = (const float*)d_in[6];
    const int*   src   = (const int*)d_in[7];
    const int*   dst   = (const int*)d_in[8];
    float* out = (float*)d_out;

    const int NB_SCAN = (N_NODES + 511) / 512;  // 196
    const size_t SMEM = (size_t)(64 * 256 + 256 * 64 + 256 + 64) * sizeof(float);
    cudaFuncSetAttribute(mlp_kernel, cudaFuncAttributeMaxDynamicSharedMemorySize, (int)SMEM);

    zero_kernel<<<(N_NODES + 255) / 256, 256>>>();
    count_kernel<<<(N_EDGES + 255) / 256, 256>>>(dst);
    scan1_kernel<<<NB_SCAN, 512>>>();
    scan2_kernel<<<1, 256>>>(NB_SCAN);
    scan3_kernel<<<NB_SCAN, 512>>>();
    scatter_kernel<<<(N_EDGES + 255) / 256, 256>>>(src, dst);
    agg_kernel<<<(N_NODES * 32 + 255) / 256, 256>>>(h);
    mlp_kernel<<<152, 256, SMEM>>>(W1, b1, W2, b2, out);
    stats_kernel<<<1024, 256>>>(out);
    bn_kernel<<<2048, 256>>>(out, gamma, beta);
}

// round 4
// speedup vs baseline: 2.1379x; 1.8335x over previous
#include <cuda_runtime.h>
#include <cuda_bf16.h>
#include <cstdint>

#define N_NODES 100000
#define N_EDGES 1600000
#define NODE_DIM 64
#define HIDDEN 256
#define OUT_DIM 64
#define BN_EPS 1e-5f
#define N_TILES 782  /* ceil(100000/128) */

// ---- device scratch (no allocation allowed) ----
__device__ float g_x[N_NODES * NODE_DIM];     // combined input x = agg/deg + h
__device__ int   g_cnt[N_NODES];
__device__ int   g_off[N_NODES + 1];
__device__ int   g_woff[N_NODES];
__device__ int   g_esrc[N_EDGES];
__device__ int   g_bsum[256];
__device__ int   g_boff[256];
__device__ float g_colsum[OUT_DIM];
__device__ float g_colsq[OUT_DIM];

// ===========================================================================
// helpers (base ISA only — no 'a'-suffix features; harness targets compute_103)
// ===========================================================================
__device__ __forceinline__ uint32_t smem_u32(const void* p) {
    uint32_t a;
    asm("{ .reg .u64 t; cvta.to.shared.u64 t, %1; cvt.u32.u64 %0, t; }" : "=r"(a) : "l"(p));
    return a;
}
__device__ __forceinline__ void ldsm4(uint32_t* r, uint32_t addr) {
    asm volatile("ldmatrix.sync.aligned.m8n8.x4.shared.b16 {%0,%1,%2,%3}, [%4];"
                 : "=r"(r[0]), "=r"(r[1]), "=r"(r[2]), "=r"(r[3]) : "r"(addr));
}
__device__ __forceinline__ void mma16816(float* d, const uint32_t* a, uint32_t b0, uint32_t b1) {
    asm volatile("mma.sync.aligned.m16n8k16.row.col.f32.bf16.bf16.f32 "
                 "{%0,%1,%2,%3}, {%4,%5,%6,%7}, {%8,%9}, {%0,%1,%2,%3};"
                 : "+f"(d[0]), "+f"(d[1]), "+f"(d[2]), "+f"(d[3])
                 : "r"(a[0]), "r"(a[1]), "r"(a[2]), "r"(a[3]), "r"(b0), "r"(b1));
}
// pack two f32 -> bf16x2 (low half = a)
__device__ __forceinline__ uint32_t packbf(float a, float b) {
    __nv_bfloat162 t = __floats2bfloat162_rn(a, b);
    return *reinterpret_cast<uint32_t*>(&t);
}
__device__ __forceinline__ float bf_lo(uint32_t p) { return __uint_as_float(p << 16); }
__device__ __forceinline__ float bf_hi(uint32_t p) { return __uint_as_float(p & 0xffff0000u); }

// ---------------------------------------------------------------------------
// 0: zero counters
// ---------------------------------------------------------------------------
__global__ void zero_kernel() {
    int i = blockIdx.x * 256 + threadIdx.x;
    if (i < N_NODES) g_cnt[i] = 0;
    if (i < OUT_DIM) { g_colsum[i] = 0.0f; g_colsq[i] = 0.0f; }
    if (i == 0) g_off[N_NODES] = N_EDGES;
}

// ---------------------------------------------------------------------------
// 1: in-degree histogram
// ---------------------------------------------------------------------------
__global__ void count_kernel(const int* __restrict__ dst) {
    int i = blockIdx.x * 256 + threadIdx.x;
    if (i < N_EDGES) atomicAdd(&g_cnt[dst[i]], 1);
}

// ---------------------------------------------------------------------------
// 2a/2b/2c: scan for CSR offsets
// ---------------------------------------------------------------------------
__global__ void scan1_kernel() {
    __shared__ int ws[16];
    int i = blockIdx.x * 512 + threadIdx.x;
    int v = (i < N_NODES) ? g_cnt[i] : 0;
#pragma unroll
    for (int d = 16; d; d >>= 1) v += __shfl_down_sync(0xffffffffu, v, d);
    if ((threadIdx.x & 31) == 0) ws[threadIdx.x >> 5] = v;
    __syncthreads();
    if (threadIdx.x == 0) {
        int s = 0;
#pragma unroll
        for (int k = 0; k < 16; k++) s += ws[k];
        g_bsum[blockIdx.x] = s;
    }
}

__global__ void scan2_kernel(int nb) {
    __shared__ int sm[256];
    int t = threadIdx.x;
    int v = (t < nb) ? g_bsum[t] : 0;
    sm[t] = v;
    __syncthreads();
    for (int d = 1; d < 256; d <<= 1) {
        int y = (t >= d) ? sm[t - d] : 0;
        __syncthreads();
        sm[t] += y;
        __syncthreads();
    }
    if (t < nb) g_boff[t] = sm[t] - v;
}

__global__ void scan3_kernel() {
    __shared__ int ws[16];
    int t = threadIdx.x, lane = t & 31, wid = t >> 5;
    int i = blockIdx.x * 512 + t;
    int c = (i < N_NODES) ? g_cnt[i] : 0;
    int x = c;
#pragma unroll
    for (int d = 1; d < 32; d <<= 1) {
        int y = __shfl_up_sync(0xffffffffu, x, d);
        if (lane >= d) x += y;
    }
    if (lane == 31) ws[wid] = x;
    __syncthreads();
    if (wid == 0) {
        int w = (lane < 16) ? ws[lane] : 0;
        int xs = w;
#pragma unroll
        for (int d = 1; d < 16; d <<= 1) {
            int y = __shfl_up_sync(0xffffffffu, xs, d);
            if (lane >= d) xs += y;
        }
        if (lane < 16) ws[lane] = xs - w;
    }
    __syncthreads();
    int excl = x - c + ws[wid] + g_boff[blockIdx.x];
    if (i < N_NODES) { g_off[i] = excl; g_woff[i] = excl; }
}

// ---------------------------------------------------------------------------
// 3: scatter edges into CSR bins
// ---------------------------------------------------------------------------
__global__ void scatter_kernel(const int* __restrict__ src,
                               const int* __restrict__ dst) {
    int i = blockIdx.x * 256 + threadIdx.x;
    if (i >= N_EDGES) return;
    int d = dst[i];
    int pos = atomicAdd(&g_woff[d], 1);
    g_esrc[pos] = src[i];
}

// ---------------------------------------------------------------------------
// 4: warp-per-node gather + mean + combine: g_x = agg/max(deg,1) + h
// ---------------------------------------------------------------------------
__global__ void agg_kernel(const float* __restrict__ h) {
    int n = (blockIdx.x * 256 + threadIdx.x) >> 5;
    if (n >= N_NODES) return;
    int lane = threadIdx.x & 31;
    int beg = __ldg(&g_off[n]);
    int end = __ldg(&g_off[n + 1]);
    float ax = 0.0f, ay = 0.0f;
    for (int j = beg; j < end; j += 32) {
        int r = end - j;
        int s_l = 0;
        if (lane < r) s_l = __ldg(&g_esrc[j + lane]);
        int cnt = r < 32 ? r : 32;
        for (int jj = 0; jj < cnt; jj++) {
            int s = __shfl_sync(0xffffffffu, s_l, jj);
            float2 v = *(const float2*)(h + ((size_t)s << 6) + (lane << 1));
            ax += v.x;
            ay += v.y;
        }
    }
    float inv = 1.0f / fmaxf((float)(end - beg), 1.0f);
    float2 hv = *(const float2*)(h + ((size_t)n << 6) + (lane << 1));
    float2 xv = make_float2(fmaf(ax, inv, hv.x), fmaf(ay, inv, hv.y));
    *(float2*)(g_x + ((size_t)n << 6) + (lane << 1)) = xv;
}

// ---------------------------------------------------------------------------
// 5: warp-MMA bf16 split-precision fused MLP.
//    Per 128-node tile, per warp (16 rows): GEMM1 m16 x n256 x k64, epilogue
//    repacks relu(H+b1) C-fragments straight into GEMM2 A-fragments (registers
//    only), GEMM2 m16 x n64 x k256, relu(+b2) -> out. 3-term bf16 split.
// ---------------------------------------------------------------------------
// smem byte offsets (bf16 tiles padded +8 elems/row for conflict-free ldmatrix)
#define SM_XH  0          /* x  hi  [128][72] bf16 */
#define SM_XL  18432      /* x  lo  */
#define SM_W1H 36864      /* W1T hi [256][72] bf16 (64 k used) */
#define SM_W1L 73728
#define SM_W2H 110592     /* W2T hi [64][264] bf16 (256 k used) */
#define SM_W2L 144384
#define SM_B1  178176     /* float[256] */
#define SM_B2  179200     /* float[64]  */
#define SMEM_MLP 179456

__global__ void __launch_bounds__(256, 1)
mlp_mma_kernel(const float* __restrict__ W1, const float* __restrict__ b1,
               const float* __restrict__ W2, const float* __restrict__ b2,
               float* __restrict__ out) {
    extern __shared__ __align__(16) char sm[];
    const uint32_t sbase = smem_u32(sm);
    int tid = threadIdx.x, lane = tid & 31, wid = tid >> 5;

    // ---- one-time weight conversion: W1T/W2T bf16 hi+lo ----
    __nv_bfloat16* w1h = (__nv_bfloat16*)(sm + SM_W1H);
    __nv_bfloat16* w1l = (__nv_bfloat16*)(sm + SM_W1L);
    for (int idx = tid; idx < 64 * 256; idx += 256) {   // W1[k][n] -> W1T[n][k]
        int k = idx >> 8, n = idx & 255;
        float w = W1[idx];
        __nv_bfloat16 hv = __float2bfloat16(w);
        w1h[n * 72 + k] = hv;
        w1l[n * 72 + k] = __float2bfloat16(w - __bfloat162float(hv));
    }
    __nv_bfloat16* w2h = (__nv_bfloat16*)(sm + SM_W2H);
    __nv_bfloat16* w2l = (__nv_bfloat16*)(sm + SM_W2L);
    for (int idx = tid; idx < 256 * 64; idx += 256) {   // W2[k][n] -> W2T[n][k]
        int k = idx >> 6, n = idx & 63;
        float w = W2[idx];
        __nv_bfloat16 hv = __float2bfloat16(w);
        w2h[n * 264 + k] = hv;
        w2l[n * 264 + k] = __float2bfloat16(w - __bfloat162float(hv));
    }
    ((float*)(sm + SM_B1))[tid & 255] = b1[tid & 255];
    if (tid < 64) ((float*)(sm + SM_B2))[tid] = b2[tid];
    __syncthreads();

    __nv_bfloat16* xh = (__nv_bfloat16*)(sm + SM_XH);
    __nv_bfloat16* xl = (__nv_bfloat16*)(sm + SM_XL);
    const float* b1s = (const float*)(sm + SM_B1);
    const float* b2s = (const float*)(sm + SM_B2);

    for (int tile = blockIdx.x; tile < N_TILES; tile += gridDim.x) {
        // ---- stage x tile -> bf16 hi/lo (thread t: row t/2, half t&1) ----
        {
            int r = tid >> 1;
            int node = tile * 128 + r;
            int co = (tid & 1) * 32;
            const float4* p = (const float4*)(g_x + (size_t)node * 64 + co);
            __nv_bfloat16* dh = xh + r * 72 + co;
            __nv_bfloat16* dl = xl + r * 72 + co;
#pragma unroll
            for (int q = 0; q < 8; q++) {
                float4 v = (node < N_NODES) ? p[q] : make_float4(0.f, 0.f, 0.f, 0.f);
                float vv[4] = {v.x, v.y, v.z, v.w};
#pragma unroll
                for (int j = 0; j < 4; j++) {
                    __nv_bfloat16 hv = __float2bfloat16(vv[j]);
                    dh[4 * q + j] = hv;
                    dl[4 * q + j] = __float2bfloat16(vv[j] - __bfloat162float(hv));
                }
            }
        }
        __syncthreads();

        // ---- A1 fragments (rows wid*16..+16, k=64 -> 4 k16 tiles) ----
        uint32_t a1h[4][4], a1l[4][4];
#pragma unroll
        for (int kt = 0; kt < 4; kt++) {
            uint32_t addr = sbase + SM_XH +
                (uint32_t)(wid * 16 + (lane & 15)) * 144u + (uint32_t)(kt * 16 + ((lane >> 4) << 3)) * 2u;
            ldsm4(a1h[kt], addr);
            ldsm4(a1l[kt], addr + (SM_XL - SM_XH));
        }

        float d2[8][4];
#pragma unroll
        for (int i = 0; i < 8; i++)
#pragma unroll
            for (int j = 0; j < 4; j++) d2[i][j] = 0.0f;

#pragma unroll 1
        for (int nc = 0; nc < 16; nc++) {
            // ---- GEMM1: H chunk n16 = [nc*16, nc*16+16) ----
            float c0[4] = {0.f, 0.f, 0.f, 0.f}, c1[4] = {0.f, 0.f, 0.f, 0.f};
            uint32_t bb = sbase + SM_W1H +
                (uint32_t)(nc * 16 + (lane & 7) + ((lane >> 4) & 1) * 8) * 144u + ((lane >> 3) & 1) * 16u;
#pragma unroll
            for (int kt = 0; kt < 4; kt++) {
                uint32_t bh[4], bl[4];
                ldsm4(bh, bb + kt * 32u);
                ldsm4(bl, bb + kt * 32u + (SM_W1L - SM_W1H));
                mma16816(c0, a1h[kt], bh[0], bh[1]);
                mma16816(c1, a1h[kt], bh[2], bh[3]);
                mma16816(c0, a1h[kt], bl[0], bl[1]);
                mma16816(c1, a1h[kt], bl[2], bl[3]);
                mma16816(c0, a1l[kt], bh[0], bh[1]);
                mma16816(c1, a1l[kt], bh[2], bh[3]);
            }
            // ---- epilogue1: relu(H+b1) -> A2 fragments (registers only) ----
            int cb = nc * 16 + (lane & 3) * 2;
            float2 bb0 = *(const float2*)&b1s[cb];
            float2 bb1 = *(const float2*)&b1s[cb + 8];
            float v00 = fmaxf(c0[0] + bb0.x, 0.f), v01 = fmaxf(c0[1] + bb0.y, 0.f);
            float v10 = fmaxf(c0[2] + bb0.x, 0.f), v11 = fmaxf(c0[3] + bb0.y, 0.f);
            float w00 = fmaxf(c1[0] + bb1.x, 0.f), w01 = fmaxf(c1[1] + bb1.y, 0.f);
            float w10 = fmaxf(c1[2] + bb1.x, 0.f), w11 = fmaxf(c1[3] + bb1.y, 0.f);
            uint32_t a2h[4], a2l[4];
            a2h[0] = packbf(v00, v01); a2l[0] = packbf(v00 - bf_lo(a2h[0]), v01 - bf_hi(a2h[0]));
            a2h[1] = packbf(v10, v11); a2l[1] = packbf(v10 - bf_lo(a2h[1]), v11 - bf_hi(a2h[1]));
            a2h[2] = packbf(w00, w01); a2l[2] = packbf(w00 - bf_lo(a2h[2]), w01 - bf_hi(a2h[2]));
            a2h[3] = packbf(w10, w11); a2l[3] = packbf(w10 - bf_lo(a2h[3]), w11 - bf_hi(a2h[3]));
            // ---- GEMM2: accumulate k16 chunk into all 64 outputs ----
            uint32_t b2b = sbase + SM_W2H +
                (uint32_t)((lane & 7) + ((lane >> 4) & 1) * 8) * 528u + (uint32_t)nc * 32u + ((lane >> 3) & 1) * 16u;
#pragma unroll
            for (int np = 0; np < 4; np++) {
                uint32_t bh[4], bl[4];
                ldsm4(bh, b2b + (uint32_t)np * (16u * 528u));
                ldsm4(bl, b2b + (uint32_t)np * (16u * 528u) + (SM_W2L - SM_W2H));
                mma16816(d2[2 * np],     a2h, bh[0], bh[1]);
                mma16816(d2[2 * np + 1], a2h, bh[2], bh[3]);
                mma16816(d2[2 * np],     a2h, bl[0], bl[1]);
                mma16816(d2[2 * np + 1], a2h, bl[2], bl[3]);
                mma16816(d2[2 * np],     a2l, bh[0], bh[1]);
                mma16816(d2[2 * np + 1], a2l, bh[2], bh[3]);
            }
        }

        // ---- epilogue2: relu(D2+b2) -> out ----
        int row0 = tile * 128 + wid * 16 + (lane >> 2);
        int colb = (lane & 3) * 2;
#pragma unroll
        for (int t = 0; t < 8; t++) {
            int col = t * 8 + colb;
            if (row0 < N_NODES) {
                float2 o;
                o.x = fmaxf(d2[t][0] + b2s[col], 0.f);
                o.y = fmaxf(d2[t][1] + b2s[col + 1], 0.f);
                *(float2*)(out + (size_t)row0 * 64 + col) = o;
            }
            if (row0 + 8 < N_NODES) {
                float2 o;
                o.x = fmaxf(d2[t][2] + b2s[col], 0.f);
                o.y = fmaxf(d2[t][3] + b2s[col + 1], 0.f);
                *(float2*)(out + (size_t)(row0 + 8) * 64 + col) = o;
            }
        }
        __syncthreads();
    }
}

// ---------------------------------------------------------------------------
// 6: BN column stats
// ---------------------------------------------------------------------------
__global__ void stats_kernel(const float* __restrict__ y) {
    __shared__ float ss[64], sq[64];
    if (threadIdx.x < 64) { ss[threadIdx.x] = 0.0f; sq[threadIdx.x] = 0.0f; }
    __syncthreads();
    const float4* y4 = (const float4*)y;
    const int total = N_NODES * 16;
    int i0 = blockIdx.x * 256 + threadIdx.x;
    int c4 = (i0 & 15) << 2;
    float4 s = make_float4(0.f, 0.f, 0.f, 0.f);
    float4 q = make_float4(0.f, 0.f, 0.f, 0.f);
    for (int i = i0; i < total; i += gridDim.x * 256) {
        float4 v = y4[i];
        s.x += v.x; s.y += v.y; s.z += v.z; s.w += v.w;
        q.x = fmaf(v.x, v.x, q.x);
        q.y = fmaf(v.y, v.y, q.y);
        q.z = fmaf(v.z, v.z, q.z);
        q.w = fmaf(v.w, v.w, q.w);
    }
    atomicAdd(&ss[c4 + 0], s.x); atomicAdd(&ss[c4 + 1], s.y);
    atomicAdd(&ss[c4 + 2], s.z); atomicAdd(&ss[c4 + 3], s.w);
    atomicAdd(&sq[c4 + 0], q.x); atomicAdd(&sq[c4 + 1], q.y);
    atomicAdd(&sq[c4 + 2], q.z); atomicAdd(&sq[c4 + 3], q.w);
    __syncthreads();
    if (threadIdx.x < 64) {
        atomicAdd(&g_colsum[threadIdx.x], ss[threadIdx.x]);
        atomicAdd(&g_colsq[threadIdx.x], sq[threadIdx.x]);
    }
}

// ---------------------------------------------------------------------------
// 7: BN apply in place
// ---------------------------------------------------------------------------
__global__ void bn_kernel(float* __restrict__ y,
                          const float* __restrict__ gamma,
                          const float* __restrict__ beta) {
    __shared__ float scale[64], shift[64];
    if (threadIdx.x < 64) {
        int c = threadIdx.x;
        const float invN = 1.0f / (float)N_NODES;
        float mean = g_colsum[c] * invN;
        float var = fmaxf(g_colsq[c] * invN - mean * mean, 0.0f);
        float sc = gamma[c] * rsqrtf(var + BN_EPS);
        scale[c] = sc;
        shift[c] = beta[c] - mean * sc;
    }
    __syncthreads();
    int i = blockIdx.x * blockDim.x + threadIdx.x;
    int stride = gridDim.x * blockDim.x;
    const int total4 = N_NODES * OUT_DIM / 4;
    float4* y4 = (float4*)y;
    for (; i < total4; i += stride) {
        int c4 = (i & 15) * 4;
        float4 v = y4[i];
        v.x = fmaf(v.x, scale[c4 + 0], shift[c4 + 0]);
        v.y = fmaf(v.y, scale[c4 + 1], shift[c4 + 1]);
        v.z = fmaf(v.z, scale[c4 + 2], shift[c4 + 2]);
        v.w = fmaf(v.w, scale[c4 + 3], shift[c4 + 3]);
        y4[i] = v;
    }
}

// ---------------------------------------------------------------------------
extern "C" void kernel_launch(void* const* d_in, const int* in_sizes, int n_in,
                              void* d_out, int out_size) {
    const float* h     = (const float*)d_in[0];
    const float* W1    = (const float*)d_in[1];
    const float* b1    = (const float*)d_in[2];
    const float* W2    = (const float*)d_in[3];
    const float* b2    = (const float*)d_in[4];
    const float* gamma = (const float*)d_in[5];
    const float* beta  = (const float*)d_in[6];
    const int*   src   = (const int*)d_in[7];
    const int*   dst   = (const int*)d_in[8];
    float* out = (float*)d_out;

    const int NB_SCAN = (N_NODES + 511) / 512;
    cudaFuncSetAttribute(mlp_mma_kernel, cudaFuncAttributeMaxDynamicSharedMemorySize, SMEM_MLP);

    zero_kernel<<<(N_NODES + 255) / 256, 256>>>();
    count_kernel<<<(N_EDGES + 255) / 256, 256>>>(dst);
    scan1_kernel<<<NB_SCAN, 512>>>();
    scan2_kernel<<<1, 256>>>(NB_SCAN);
    scan3_kernel<<<NB_SCAN, 512>>>();
    scatter_kernel<<<(N_EDGES + 255) / 256, 256>>>(src, dst);
    agg_kernel<<<(N_NODES * 32 + 255) / 256, 256>>>(h);
    mlp_mma_kernel<<<148, 256, SMEM_MLP>>>(W1, b1, W2, b2, out);
    stats_kernel<<<1024, 256>>>(out);
    bn_kernel<<<2048, 256>>>(out, gamma, beta);
}